// round 2
// baseline (speedup 1.0000x reference)
#include <cuda_runtime.h>
#include <cuda_bf16.h>
#include <cstdint>

// Problem constants (match reference)
#define LVL   32
#define PINS  131072
#define KF    2
#define NNETS 1000000
#define TPER  10.0f

static __device__ __forceinline__ void atomicMinFloat(float* addr, float val) {
    // Signed/unsigned trick; initial value (TPER=10.0) is positive, so the
    // representation invariant holds for all intermediate states.
    if (val >= 0.0f) {
        atomicMin((int*)addr, __float_as_int(val));
    } else {
        atomicMax((unsigned int*)addr, __float_as_uint(val));
    }
}

// mask element is a 4-byte word (float32 0.0/1.0 or int32 0/1): nonzero bits = ignored net
static __device__ __forceinline__ bool net_ignored(const unsigned int* __restrict__ mask, int n) {
    return mask[n] != 0u;
}

// Initialize: arrival level 0 = delays[0:P], required (all levels) = TPER.
__global__ void sta_init_kernel(const float* __restrict__ delays,
                                float* __restrict__ arr,
                                float* __restrict__ req) {
    int i = blockIdx.x * blockDim.x + threadIdx.x;
    if (i < LVL * PINS) {
        req[i] = TPER;
        if (i < PINS) arr[i] = delays[i];
    }
}

// Forward arrival propagation for level l (1..L-1).
__global__ void sta_fwd_kernel(const float* __restrict__ delays,
                               const int2*  __restrict__ src,   // [(L-1)*P] pairs
                               const int2*  __restrict__ net,   // [(L-1)*P] pairs
                               const unsigned int* __restrict__ mask,
                               float* __restrict__ arr,
                               int l) {
    int p = blockIdx.x * blockDim.x + threadIdx.x;
    if (p >= PINS) return;

    float d = delays[l * PINS + p];
    int2  s = src[(l - 1) * PINS + p];
    int2  n = net[(l - 1) * PINS + p];
    const float* ap = arr + (l - 1) * PINS;

    float m = d;
    if (!net_ignored(mask, n.x)) m = fmaxf(m, ap[s.x] + d);
    if (!net_ignored(mask, n.y)) m = fmaxf(m, ap[s.y] + d);

    arr[l * PINS + p] = m;
}

// Backward required propagation: scatter-min from level l+1 pins into level l.
__global__ void sta_bwd_kernel(const float* __restrict__ delays,
                               const int2*  __restrict__ src,
                               const int2*  __restrict__ net,
                               const unsigned int* __restrict__ mask,
                               float* __restrict__ req,
                               int l) {
    int p = blockIdx.x * blockDim.x + threadIdx.x;
    if (p >= PINS) return;

    float c = req[(l + 1) * PINS + p] - delays[(l + 1) * PINS + p];
    int2  s = src[l * PINS + p];
    int2  n = net[l * PINS + p];
    float* rl = req + l * PINS;

    if (!net_ignored(mask, n.x)) atomicMinFloat(rl + s.x, c);
    if (!net_ignored(mask, n.y)) atomicMinFloat(rl + s.y, c);
}

// Finalize: slacks = req - arr; mask re-emitted as float 0/1.
__global__ void sta_final_kernel(const float* __restrict__ arr,
                                 const float* __restrict__ req,
                                 const unsigned int* __restrict__ mask,
                                 float* __restrict__ out,
                                 long long out_size) {
    long long i = (long long)blockIdx.x * blockDim.x + threadIdx.x;
    const long long LP = (long long)LVL * PINS;
    if (i < LP) {
        long long o = 2 * LP + i;
        if (o < out_size) out[o] = req[i] - arr[i];
    }
    if (i < NNETS) {
        long long o = 3 * LP + i;
        if (o < out_size) out[o] = mask[i] ? 1.0f : 0.0f;
    }
}

extern "C" void kernel_launch(void* const* d_in, const int* in_sizes, int n_in,
                              void* d_out, int out_size) {
    const float*        delays = (const float*)d_in[0];
    const int2*         src    = (const int2*)d_in[1];   // K=2 packed pairs
    const int2*         net    = (const int2*)d_in[2];
    const unsigned int* mask   = (const unsigned int*)d_in[3]; // 4-byte bool

    float* out = (float*)d_out;
    const long long LP = (long long)LVL * PINS;

    // arrival and required live directly in the output buffer
    float* arr = out;            // [0, LP)
    float* req = out + LP;       // [LP, 2LP)

    const int T = 256;
    const int blocksP  = (PINS + T - 1) / T;          // 512
    const int blocksLP = (int)((LP + T - 1) / T);     // 16384

    sta_init_kernel<<<blocksLP, T>>>(delays, arr, req);

    // forward levels 1..L-1 (sequential dependency)
    for (int l = 1; l < LVL; ++l) {
        sta_fwd_kernel<<<blocksP, T>>>(delays, src, net, mask, arr, l);
    }

    // backward levels L-2..0 (sequential dependency)
    for (int l = LVL - 2; l >= 0; --l) {
        sta_bwd_kernel<<<blocksP, T>>>(delays, src, net, mask, req, l);
    }

    // slacks + mask tail
    long long maxN = (LP > (long long)NNETS) ? LP : (long long)NNETS;
    int blocksF = (int)((maxN + T - 1) / T);
    sta_final_kernel<<<blocksF, T>>>(arr, req, mask, out, (long long)out_size);
}